// round 14
// baseline (speedup 1.0000x reference)
#include <cuda_runtime.h>
#include <cuda_bf16.h>

#define N_NODES 100000
#define N_EDGES 6400000
#define NBLK    391          // ceil(N_NODES/256)

// ---------------- scratch (allocation-free __device__ globals) ----------------
__device__ int    g_deg  [N_NODES];     // in-degree (no self-loop)
__device__ float  g_dinv [N_NODES];     // rsqrt(deg+1)
__device__ int    g_rowp [N_NODES];     // CSR row start (grouped by dst)
__device__ int    g_cur  [N_NODES];     // fill cursors
__device__ int    g_part [NBLK];        // scan partials
__device__ int    g_poff [NBLK];        // scan offsets
__device__ int    g_csrc [N_EDGES];     // CSR: src ids grouped by dst
__device__ float4 g_p4   [N_NODES];     // raw x@W1
__device__ float4 g_f4a  [N_NODES];     // scaled features L1
__device__ float4 g_f4b  [N_NODES];     // scaled features L2
__device__ float2 g_f2   [N_NODES];     // scaled features L3

__device__ __forceinline__ int clampN(int v) {
    return min(max(v, 0), N_NODES - 1);
}

// ---------------- degree ----------------
__global__ void k_deg_count(const int* __restrict__ dst) {
    int e = blockIdx.x * blockDim.x + threadIdx.x;
    if (e < N_EDGES) atomicAdd(&g_deg[clampN(dst[e])], 1);
}

// ---------------- prefix scan of degrees -> row pointers (proven in R11) ------
__global__ void k_scan1() {
    int t = threadIdx.x;
    int n = blockIdx.x * 256 + t;
    int lane = t & 31, w = t >> 5;
    int v = (n < N_NODES) ? g_deg[n] : 0;
#pragma unroll
    for (int o = 16; o > 0; o >>= 1) v += __shfl_down_sync(0xFFFFFFFFu, v, o);
    __shared__ int sh[8];
    if (lane == 0) sh[w] = v;
    __syncthreads();
    if (w == 0) {
        int s = (lane < 8) ? sh[lane] : 0;
#pragma unroll
        for (int o = 16; o > 0; o >>= 1) s += __shfl_down_sync(0xFFFFFFFFu, s, o);
        if (lane == 0) g_part[blockIdx.x] = s;
    }
}

__global__ void k_scan2() {
    __shared__ int s[512];
    int t = threadIdx.x;
    int mine = (t < NBLK) ? g_part[t] : 0;
    s[t] = mine;
    __syncthreads();
    for (int o = 1; o < 512; o <<= 1) {
        int v = (t >= o) ? s[t - o] : 0;
        __syncthreads();
        s[t] += v;
        __syncthreads();
    }
    if (t < NBLK) g_poff[t] = s[t] - mine;        // exclusive
}

__global__ void k_scan3() {
    int t = threadIdx.x, b = blockIdx.x;
    int n = b * 256 + t;
    int lane = t & 31, w = t >> 5;
    int d = (n < N_NODES) ? g_deg[n] : 0;
    int v = d;
#pragma unroll
    for (int o = 1; o < 32; o <<= 1) {
        int u = __shfl_up_sync(0xFFFFFFFFu, v, o);
        if (lane >= o) v += u;
    }
    __shared__ int wsum[8];
    if (lane == 31) wsum[w] = v;
    __syncthreads();
    if (w == 0) {
        int s = (lane < 8) ? wsum[lane] : 0;
#pragma unroll
        for (int o = 1; o < 8; o <<= 1) {
            int u = __shfl_up_sync(0xFFFFFFFFu, s, o);
            if (lane >= o) s += u;
        }
        if (lane < 8) wsum[lane] = s;
    }
    __syncthreads();
    if (n < N_NODES) {
        int excl = v - d + (w > 0 ? wsum[w - 1] : 0) + g_poff[b];
        g_rowp[n] = excl;
        g_cur[n]  = excl;
        g_dinv[n] = rsqrtf((float)(d + 1));       // +1 self-loop
    }
}

// ---------------- CSR fill ----------------
__global__ void k_fill(const int* __restrict__ src, const int* __restrict__ dst) {
    int e = blockIdx.x * blockDim.x + threadIdx.x;
    if (e >= N_EDGES) return;
    int s = clampN(src[e]);
    int d = clampN(dst[e]);
    int pos = atomicAdd(&g_cur[d], 1);
    g_csrc[pos] = s;
}

// ---------------- layer 1 raw matmul: p4 = x @ W1 (vectorized, R12-proven) ----
__global__ void k_mm1(const float* __restrict__ x, const float* __restrict__ W1) {
    __shared__ float4 sW[128];
    __shared__ float  sx[8][128];
    int t = threadIdx.x;
    if (t < 128) sW[t] = ((const float4*)W1)[t];

    int base = blockIdx.x * 8;                    // 12500 * 8 == 100000 exactly
    float4 v = ((const float4*)(x + (size_t)base * 128))[t];
    ((float4*)sx)[t] = v;
    __syncthreads();

    int warp = t >> 5;
    int lane = t & 31;
    float p0 = 0.f, p1 = 0.f, p2 = 0.f, p3 = 0.f;
#pragma unroll
    for (int i = 0; i < 4; i++) {
        int k = lane + 32 * i;
        float xv = sx[warp][k];
        float4 w = sW[k];
        p0 += xv * w.x; p1 += xv * w.y; p2 += xv * w.z; p3 += xv * w.w;
    }
#pragma unroll
    for (int off = 16; off > 0; off >>= 1) {
        p0 += __shfl_down_sync(0xFFFFFFFFu, p0, off);
        p1 += __shfl_down_sync(0xFFFFFFFFu, p1, off);
        p2 += __shfl_down_sync(0xFFFFFFFFu, p2, off);
        p3 += __shfl_down_sync(0xFFFFFFFFu, p3, off);
    }
    if (lane == 0)
        g_p4[base + warp] = make_float4(p0, p1, p2, p3);
}

// ---------------- scale: f4a = p4 * dinv ----------------
__global__ void k_scale() {
    int n = blockIdx.x * blockDim.x + threadIdx.x;
    if (n >= N_NODES) return;
    float di = g_dinv[n];
    float4 p = g_p4[n];
    g_f4a[n] = make_float4(p.x * di, p.y * di, p.z * di, p.w * di);
}

// ---------------- pull pass 1: agg(f4a) -> tanh -> W2 -> f4b (thread/node) ----
__global__ void k_pull1(const float* __restrict__ b1, const float* __restrict__ W2) {
    int n = blockIdx.x * blockDim.x + threadIdx.x;
    if (n >= N_NODES) return;
    int start = g_rowp[n];
    int len   = g_deg[n];
    float4 self = g_f4a[n];
    float a0 = self.x, a1 = self.y, a2 = self.z, a3 = self.w;   // self-loop
#pragma unroll 4
    for (int i = 0; i < len; i++) {
        int s = g_csrc[start + i];
        float4 v = g_f4a[s];
        a0 += v.x; a1 += v.y; a2 += v.z; a3 += v.w;
    }
    float di = g_dinv[n];
    float h0 = tanhf(a0 * di + b1[0]);
    float h1 = tanhf(a1 * di + b1[1]);
    float h2 = tanhf(a2 * di + b1[2]);
    float h3 = tanhf(a3 * di + b1[3]);
    float4 g;
    g.x = (h0 * W2[0] + h1 * W2[4] + h2 * W2[8]  + h3 * W2[12]) * di;
    g.y = (h0 * W2[1] + h1 * W2[5] + h2 * W2[9]  + h3 * W2[13]) * di;
    g.z = (h0 * W2[2] + h1 * W2[6] + h2 * W2[10] + h3 * W2[14]) * di;
    g.w = (h0 * W2[3] + h1 * W2[7] + h2 * W2[11] + h3 * W2[15]) * di;
    g_f4b[n] = g;
}

// ---------------- pull pass 2: agg(f4b) -> tanh -> W3 -> f2 ----------------
__global__ void k_pull2(const float* __restrict__ b2, const float* __restrict__ W3) {
    int n = blockIdx.x * blockDim.x + threadIdx.x;
    if (n >= N_NODES) return;
    int start = g_rowp[n];
    int len   = g_deg[n];
    float4 self = g_f4b[n];
    float a0 = self.x, a1 = self.y, a2 = self.z, a3 = self.w;
#pragma unroll 4
    for (int i = 0; i < len; i++) {
        int s = g_csrc[start + i];
        float4 v = g_f4b[s];
        a0 += v.x; a1 += v.y; a2 += v.z; a3 += v.w;
    }
    float di = g_dinv[n];
    float h0 = tanhf(a0 * di + b2[0]);
    float h1 = tanhf(a1 * di + b2[1]);
    float h2 = tanhf(a2 * di + b2[2]);
    float h3 = tanhf(a3 * di + b2[3]);
    float2 g;
    g.x = (h0 * W3[0] + h1 * W3[2] + h2 * W3[4] + h3 * W3[6]) * di;
    g.y = (h0 * W3[1] + h1 * W3[3] + h2 * W3[5] + h3 * W3[7]) * di;
    g_f2[n] = g;
}

// ---------------- pull pass 3: agg(f2) -> tanh -> classifier -> out ----------
__global__ void k_pull3(const float* __restrict__ b3,
                        const float* __restrict__ Wc, const float* __restrict__ bc,
                        float* __restrict__ out, float* __restrict__ hout) {
    int n = blockIdx.x * blockDim.x + threadIdx.x;
    if (n >= N_NODES) return;
    int start = g_rowp[n];
    int len   = g_deg[n];
    float2 self = g_f2[n];
    float a0 = self.x, a1 = self.y;
#pragma unroll 4
    for (int i = 0; i < len; i++) {
        int s = g_csrc[start + i];
        float2 v = g_f2[s];
        a0 += v.x; a1 += v.y;
    }
    float di = g_dinv[n];
    float h0 = tanhf(a0 * di + b3[0]);
    float h1 = tanhf(a1 * di + b3[1]);
    float* o = out + (size_t)n * 10;
#pragma unroll
    for (int j = 0; j < 10; j++)
        o[j] = h0 * Wc[j] + h1 * Wc[10 + j] + bc[j];
    hout[2 * n + 0] = h0;
    hout[2 * n + 1] = h1;
}

// ---------------- launch ----------------
extern "C" void kernel_launch(void* const* d_in, const int* in_sizes, int n_in,
                              void* d_out, int out_size) {
    const float* x  = (const float*)d_in[0];
    const int*   ei = (const int*)d_in[1];        // int32, [2, E] row-major
    const float* W1 = (const float*)d_in[2];
    const float* b1 = (const float*)d_in[3];
    const float* W2 = (const float*)d_in[4];
    const float* b2 = (const float*)d_in[5];
    const float* W3 = (const float*)d_in[6];
    const float* b3 = (const float*)d_in[7];
    const float* Wc = (const float*)d_in[8];
    const float* bc = (const float*)d_in[9];

    const int* src = ei;            // row 0
    const int* dst = ei + N_EDGES;  // row 1

    float* out  = (float*)d_out;                  // [N, 10]
    float* hout = out + (size_t)N_NODES * 10;     // [N, 2]

    void* degPtr = nullptr;
    cudaGetSymbolAddress(&degPtr, g_deg);
    cudaMemsetAsync(degPtr, 0, N_NODES * sizeof(int));

    const int T = 256;
    const int edgeBlocks = (N_EDGES + T - 1) / T;
    const int mm1Blocks  = N_NODES / 8;           // 12500, exact

    k_deg_count<<<edgeBlocks, T>>>(dst);
    k_scan1    <<<NBLK, T>>>();
    k_scan2    <<<1, 512>>>();
    k_scan3    <<<NBLK, T>>>();
    k_fill     <<<edgeBlocks, T>>>(src, dst);

    k_mm1      <<<mm1Blocks, T>>>(x, W1);
    k_scale    <<<NBLK, T>>>();

    k_pull1    <<<NBLK, T>>>(b1, W2);
    k_pull2    <<<NBLK, T>>>(b2, W3);
    k_pull3    <<<NBLK, T>>>(b3, Wc, bc, out, hout);
}